// round 12
// baseline (speedup 1.0000x reference)
#include <cuda_runtime.h>
#include <cstdint>
#include <cstddef>

#define T_STEPS 1024
#define BATCH   8
#define DIM     1024
#define NSLOTS  8
#define RANK    256
#define GROUP   16            // CTAs per slot group (= cluster size)
#define NCTAS   (NSLOTS*GROUP)

// SMEM strides (floats): odd multiples of 4 floats (16B) => 16B-aligned rows
// AND conflict-free LDS.128 column access.
#define SV_STRIDE  68          // V chunk: [256 r][64 d]   (17 float4)
#define SU_STRIDE  260         // U chunk: [64 d][256 r]   (65 float4)
#define SH_STRIDE  68          // own h:   [8 b][64 d]
#define SVH_STRIDE 260         // full Vh: [8 b][256 r]
#define MB_STRIDE  132         // mailbox: [16 src][128] (+4 pad)

#define MBAR_FLOATS 4                 // mbarR + mbarG (16 B)
#define MAIL_ELEMS  (16*MB_STRIDE)    // 2112
#define SV_ELEMS    (256*SV_STRIDE)   // 17408
#define SU_ELEMS    (64*SU_STRIDE)    // 16640
#define SH_ELEMS    (8*SH_STRIDE)     // 544
#define SVH_ELEMS   (8*SVH_STRIDE)    // 2080
#define SMEM_FLOATS (MBAR_FLOATS+MAIL_ELEMS+SV_ELEMS+SU_ELEMS+SH_ELEMS+SVH_ELEMS)
#define SMEM_BYTES  (SMEM_FLOATS*4)   // ~155 KB < 227KB

// ---------------- device scratch (static, allocation-rule-safe) ----------------
__device__ float    g_wx[(size_t)T_STEPS*BATCH*DIM];   // Wx + bias, [t][b][d]
__device__ float    g_vh3[3*NSLOTS*BATCH*RANK];        // fallback-path Vh accum
__device__ unsigned g_bar[NSLOTS];                     // fallback-path barrier

// packed fp32x2 FMA (full-rate fp32 on sm_103a; 3-reg FFMA is half rate)
__device__ __forceinline__ float2 ffma2(float2 a, float2 b, float2 c) {
    float2 d;
    asm("fma.rn.f32x2 %0, %1, %2, %3;"
        : "=l"(*reinterpret_cast<unsigned long long*>(&d))
        : "l"(*reinterpret_cast<const unsigned long long*>(&a)),
          "l"(*reinterpret_cast<const unsigned long long*>(&b)),
          "l"(*reinterpret_cast<const unsigned long long*>(&c)));
    return d;
}
__device__ __forceinline__ float2 lo2(float4 v) { return make_float2(v.x, v.y); }
__device__ __forceinline__ float2 hi2(float4 v) { return make_float2(v.z, v.w); }

// ---------------- cluster / mbarrier helpers ----------------
__device__ __forceinline__ uint32_t smem_u32(const void* p) {
    return (uint32_t)__cvta_generic_to_shared(p);
}
__device__ __forceinline__ uint32_t mapa_u32(uint32_t a, uint32_t rank) {
    uint32_t r;
    asm("mapa.shared::cluster.u32 %0, %1, %2;" : "=r"(r) : "r"(a), "r"(rank));
    return r;
}
__device__ __forceinline__ void mbar_init(uint32_t mbar, uint32_t cnt) {
    asm volatile("mbarrier.init.shared.b64 [%0], %1;" :: "r"(mbar), "r"(cnt) : "memory");
}
__device__ __forceinline__ void mbar_expect_tx(uint32_t mbar, uint32_t tx) {
    asm volatile("mbarrier.arrive.expect_tx.shared.b64 _, [%0], %1;"
                 :: "r"(mbar), "r"(tx) : "memory");
}
// fire-and-forget remote SMEM store, counted on the DEST CTA's mbarrier
__device__ __forceinline__ void st_async_f32(uint32_t dst, float v, uint32_t mbar) {
    asm volatile("st.async.weak.shared::cluster.mbarrier::complete_tx::bytes.b32 [%0], %1, [%2];"
                 :: "r"(dst), "r"(__float_as_uint(v)), "r"(mbar) : "memory");
}
__device__ __forceinline__ void mbar_wait_parity_cluster(uint32_t mbar, uint32_t parity) {
    asm volatile(
        "{\n\t"
        ".reg .pred P1;\n\t"
        "WL_%=:\n\t"
        "mbarrier.try_wait.parity.acquire.cluster.shared::cta.b64 P1, [%0], %1, 0x989680;\n\t"
        "@P1 bra.uni WD_%=;\n\t"
        "bra.uni WL_%=;\n\t"
        "WD_%=:\n\t"
        "}"
        :: "r"(mbar), "r"(parity) : "memory");
}

// ======================= kernel 1: Wx = x @ W^T + bias =======================
// (R9 proven version: 64x64 tiles, BK=32, 256 threads, 4x4/thread, 437us)
__global__ __launch_bounds__(256) void wx_kernel(const float* __restrict__ x,
                                                 const float* __restrict__ W,
                                                 const float* __restrict__ bias) {
    __shared__ float sA[64*36];
    __shared__ float sB[64*36];
    const int tid = threadIdx.x;
    const int m0 = blockIdx.y * 64;
    const int n0 = blockIdx.x * 64;
    if (blockIdx.x == 0 && blockIdx.y == 0 && tid < NSLOTS) g_bar[tid] = 0u;
    if (blockIdx.y == 0) {                // zero fallback Vh buffers
        int base = blockIdx.x * 256 + tid;
        #pragma unroll
        for (int k = 0; k < 12; k++) g_vh3[base + k*4096] = 0.f;
    }

    const int tm = tid >> 4;
    const int tn = tid & 15;

    float2 acc[4][4];
    #pragma unroll
    for (int i = 0; i < 4; i++)
        #pragma unroll
        for (int j = 0; j < 4; j++) acc[i][j] = make_float2(0.f, 0.f);

    for (int kb = 0; kb < 1024; kb += 32) {
        __syncthreads();
        #pragma unroll
        for (int it = 0; it < 2; it++) {
            int i = tid + it*256;
            int row = i >> 3, c4 = (i & 7) * 4;
            *(float4*)&sA[row*36 + c4] = *(const float4*)&x[(size_t)(m0+row)*1024 + kb + c4];
            *(float4*)&sB[row*36 + c4] = *(const float4*)&W[(size_t)(n0+row)*1024 + kb + c4];
        }
        __syncthreads();
        #pragma unroll
        for (int kk = 0; kk < 32; kk += 4) {
            float4 a[4], b[4];
            #pragma unroll
            for (int i = 0; i < 4; i++) a[i] = *(float4*)&sA[(tm+16*i)*36 + kk];
            #pragma unroll
            for (int j = 0; j < 4; j++) b[j] = *(float4*)&sB[(tn+16*j)*36 + kk];
            #pragma unroll
            for (int i = 0; i < 4; i++)
                #pragma unroll
                for (int j = 0; j < 4; j++) {
                    acc[i][j] = ffma2(lo2(a[i]), lo2(b[j]), acc[i][j]);
                    acc[i][j] = ffma2(hi2(a[i]), hi2(b[j]), acc[i][j]);
                }
        }
    }
    #pragma unroll
    for (int i = 0; i < 4; i++) {
        int m = m0 + tm + 16*i;
        #pragma unroll
        for (int j = 0; j < 4; j++) {
            int n = n0 + tn + 16*j;
            g_wx[(size_t)m*1024 + n] = acc[i][j].x + acc[i][j].y + bias[n];
        }
    }
}

// ================== kernel 2: persistent recurrence (d-partitioned) ==================
// 128 CTAs = 8 slots x 16 d-chunks, 256 threads. ALL k-splits are intra-warp and
// reduced with shuffles — one __syncthreads per step, no sRed scratch.
// USE_CLUSTER=true : DSMEM all-reduce (st.async reduce-scatter -> owner sum -> fan-out).
// USE_CLUSTER=false: proven REDG + software-barrier path.
template <bool USE_CLUSTER>
__global__ void __launch_bounds__(256, 1)
recur_kernel_t(const float* __restrict__ h0, const float* __restrict__ U,
               const float* __restrict__ V, float* __restrict__ hout) {
    extern __shared__ float sm[];
    float* sMbar = sm;                    // mbarR + mbarG
    float* sMail = sMbar + MBAR_FLOATS;   // [16 src][MB_STRIDE] mailbox
    float* sV    = sMail + MAIL_ELEMS;    // [256][SV_STRIDE]  V[s][r][dlo+dd]
    float* sU    = sV  + SV_ELEMS;        // [64][SU_STRIDE]   U[s][dlo+di][r]
    float* sH    = sU  + SU_ELEMS;        // [8][SH_STRIDE]    own h[b][dlo+dd]
    float* sVh   = sH  + SH_ELEMS;        // [8][SVH_STRIDE]   summed Vh[b][r]

    const int tid  = threadIdx.x;
    const int lane = tid & 31;
    const int w    = tid >> 5;            // 8 warps
    const int s    = blockIdx.x >> 4;
    const int rk   = blockIdx.x & 15;     // cluster rank
    const int dlo  = rk * 64;

    const uint32_t mbarR = smem_u32(sMbar);
    const uint32_t mbarG = mbarR + 8;

    if (USE_CLUSTER) {
        if (tid == 0) { mbar_init(mbarR, 1); mbar_init(mbarG, 1); }
    }

    // resident weights (float4)
    #pragma unroll
    for (int k = 0; k < 16; k++) {          // V chunk (256 rows x 16 f4)
        int i = tid + k*256;
        int row = i >> 4, c4 = (i & 15) * 4;
        *(float4*)&sV[row*SV_STRIDE + c4] =
            *(const float4*)&V[((size_t)(s*256 + row))*1024 + dlo + c4];
    }
    #pragma unroll
    for (int k = 0; k < 16; k++) {          // U chunk (64 rows x 64 f4)
        int i = tid + k*256;
        int row = i >> 6, c4 = (i & 63) * 4;
        *(float4*)&sU[row*SU_STRIDE + c4] =
            *(const float4*)&U[((size_t)(s*1024 + dlo + row))*256 + c4];
    }
    for (int i = tid; i < 512; i += 256) {
        int b = i >> 6, dd = i & 63;
        float v = h0[(size_t)b*8192 + s*1024 + dlo + dd];
        sH[b*SH_STRIDE + dd] = v;
        hout[(size_t)s*8192 + b*1024 + dlo + dd] = v;
    }
    __syncthreads();
    if (USE_CLUSTER) {
        // mbarrier inits must be cluster-visible before any st.async arrives
        asm volatile("barrier.cluster.arrive.aligned;" ::: "memory");
        asm volatile("barrier.cluster.wait.aligned;"   ::: "memory");
    }

    // ---- GEMM1 map: warp w covers r = w*16 + (lane&15) and +128; lane>>4 = d-half
    const int rA   = w*16 + (lane & 15);
    const int db1  = (lane >> 4) * 32;     // d base for this lane's half
    const int rSend = (lane < 16) ? rA : (rA + 128);
    const int ownerR = rSend >> 4;         // owner CTA rank for my r
    const int rl     = lane & 15;          // r within owner's 16-chunk
    const uint32_t mboxR_remote = USE_CLUSTER
        ? mapa_u32(smem_u32(&sMail[rk*MB_STRIDE + rl]), (uint32_t)ownerR) : 0u;
    const uint32_t mbarR_remote = USE_CLUSTER
        ? mapa_u32(mbarR, (uint32_t)ownerR) : 0u;
    // owner-stage source offset (tid<128): b = tid>>4, rl2 = tid&15
    const uint32_t sVh_off = USE_CLUSTER
        ? smem_u32(&sVh[(tid >> 4)*SVH_STRIDE + rk*16 + (tid & 15)]) : 0u;

    // ---- GEMM2 map: q2 = lane&3 -> d offset, s2 = lane>>2 -> r slice
    const int q2 = lane & 3;
    const int s2 = lane >> 2;              // 0..7
    const int dA = w*4 + q2;               // outputs d = dA and dA+32
    // final ownership after 3 predicated bfly rounds:
    const int jE  = (lane >> 2) & 1;                        // d-pair select
    const int bE0 = ((lane >> 3) & 1) * 4 + ((lane >> 4) & 1) * 2;
    const int dE  = dA + jE * 32;                           // my epilogue d

    for (int t = 0; t < T_STEPS; t++) {
        // prefetch this step's Wx values for my 2 epilogue outputs
        const float* wxrow = g_wx + (size_t)t * 8192;
        float wxp0 = wxrow[(bE0    )*1024 + dlo + dE];
        float wxp1 = wxrow[(bE0 + 1)*1024 + dlo + dE];

        __syncthreads();   // sH fully written by previous epilogue

        if (USE_CLUSTER && tid == 0) {
            mbar_expect_tx(mbarR, 8192u);
            mbar_expect_tx(mbarG, 8192u);
        }

        // ---- GEMM1: Vh partials, intra-warp 2-way d-split ----
        float sv[8];   // my r's 8 b-sums (after shuffle)
        {
            float2 acc[16];   // [ri*8 + b], ri: 0=rA, 1=rA+128
            #pragma unroll
            for (int i = 0; i < 16; i++) acc[i] = make_float2(0.f, 0.f);
            #pragma unroll
            for (int dd = 0; dd < 32; dd += 4) {
                int d = db1 + dd;
                float4 v0 = *(float4*)&sV[rA*SV_STRIDE + d];
                float4 v1 = *(float4*)&sV[(rA+128)*SV_STRIDE + d];
                #pragma unroll
                for (int b = 0; b < 8; b++) {
                    float4 hh = *(float4*)&sH[b*SH_STRIDE + d];   // broadcast
                    acc[b]   = ffma2(lo2(v0), lo2(hh), acc[b]);
                    acc[b]   = ffma2(hi2(v0), hi2(hh), acc[b]);
                    acc[8+b] = ffma2(lo2(v1), lo2(hh), acc[8+b]);
                    acc[8+b] = ffma2(hi2(v1), hi2(hh), acc[8+b]);
                }
            }
            float x[16];
            #pragma unroll
            for (int i = 0; i < 16; i++) x[i] = acc[i].x + acc[i].y;
            #pragma unroll
            for (int i = 0; i < 16; i++)
                x[i] += __shfl_xor_sync(0xffffffffu, x[i], 16);
            // lane<16 owns rA (x[0..7]); lane>=16 owns rA+128 (x[8..15])
            #pragma unroll
            for (int b = 0; b < 8; b++)
                sv[b] = (lane < 16) ? x[b] : x[8+b];
        }

        if (USE_CLUSTER) {
            // reduce-scatter: send my 8 b-values to my r's owner
            #pragma unroll
            for (int b = 0; b < 8; b++)
                st_async_f32(mboxR_remote + (uint32_t)(b*16*4), sv[b], mbarR_remote);
            // owners (tid<128): wait all 16 sources, sum, fan out to all CTAs
            if (tid < 128) {
                mbar_wait_parity_cluster(mbarR, (uint32_t)(t & 1));
                float ssum = 0.f;
                #pragma unroll
                for (int i = 0; i < 16; i++) ssum += sMail[i*MB_STRIDE + tid];
                #pragma unroll
                for (int c = 0; c < 16; c++) {
                    uint32_t dst = mapa_u32(sVh_off, (uint32_t)c);
                    uint32_t mb  = mapa_u32(mbarG,   (uint32_t)c);
                    st_async_f32(dst, ssum, mb);
                }
            }
            mbar_wait_parity_cluster(mbarG, (uint32_t)(t & 1));
        } else {
            // fallback: REDG into L2 triple buffer + software barrier + ldcg
            float* gbuf = g_vh3 + ((size_t)(t % 3) * NSLOTS + s) * 2048;
            #pragma unroll
            for (int b = 0; b < 8; b++)
                atomicAdd(&gbuf[b*256 + rSend], sv[b]);
            __threadfence();
            __syncthreads();
            if (tid == 0) {
                atomicAdd(&g_bar[s], 1u);
                unsigned target = (unsigned)GROUP * (unsigned)(t + 1);
                while (*((volatile unsigned*)&g_bar[s]) < target) { }
            }
            __syncthreads();
            {
                const float4* src = (const float4*)gbuf;
                #pragma unroll
                for (int k = 0; k < 2; k++) {
                    int i = tid + k*256;
                    float4 v = __ldcg(&src[i]);
                    int b = i >> 6, c4 = (i & 63) * 4;
                    *(float4*)&sVh[b*SVH_STRIDE + c4] = v;
                }
                float* zbuf = g_vh3 + ((size_t)((t + 2) % 3) * NSLOTS + s) * 2048;
                if (tid < 128) zbuf[rk*128 + tid] = 0.f;
            }
            __syncthreads();
        }

        // ---- GEMM2: Uh, intra-warp 8-way r-split (interleaved slices) ----
        float f0, f1;
        {
            float2 acc[16];   // [j*8 + b], j: 0=dA, 1=dA+32
            #pragma unroll
            for (int i = 0; i < 16; i++) acc[i] = make_float2(0.f, 0.f);
            #pragma unroll
            for (int rr = 0; rr < 8; rr++) {
                int r = s2*4 + rr*32;
                float4 u0 = *(float4*)&sU[dA*SU_STRIDE + r];
                float4 u1 = *(float4*)&sU[(dA+32)*SU_STRIDE + r];
                #pragma unroll
                for (int b = 0; b < 8; b++) {
                    float4 vh = *(float4*)&sVh[b*SVH_STRIDE + r];
                    acc[b]   = ffma2(lo2(u0), lo2(vh), acc[b]);
                    acc[b]   = ffma2(hi2(u0), hi2(vh), acc[b]);
                    acc[8+b] = ffma2(lo2(u1), lo2(vh), acc[8+b]);
                    acc[8+b] = ffma2(hi2(u1), hi2(vh), acc[8+b]);
                }
            }
            float x[16];
            #pragma unroll
            for (int i = 0; i < 16; i++) x[i] = acc[i].x + acc[i].y;
            // round 1 (mask 4): keep j = (lane>>2)&1 half -> 8 values (index = b)
            float y[8];
            #pragma unroll
            for (int i = 0; i < 8; i++) {
                float tl = x[i]   + __shfl_xor_sync(0xffffffffu, x[i],   4);
                float th = x[8+i] + __shfl_xor_sync(0xffffffffu, x[8+i], 4);
                y[i] = (lane & 4) ? th : tl;
            }
            // round 2 (mask 8): keep b-high = (lane>>3)&1 -> 4 values (index = b&3)
            float z[4];
            #pragma unroll
            for (int i = 0; i < 4; i++) {
                float tl = y[i]   + __shfl_xor_sync(0xffffffffu, y[i],   8);
                float th = y[4+i] + __shfl_xor_sync(0xffffffffu, y[4+i], 8);
                z[i] = (lane & 8) ? th : tl;
            }
            // round 3 (mask 16): keep b-mid = (lane>>4)&1 -> 2 values (index = b&1)
            {
                float tl0 = z[0] + __shfl_xor_sync(0xffffffffu, z[0], 16);
                float th0 = z[2] + __shfl_xor_sync(0xffffffffu, z[2], 16);
                float tl1 = z[1] + __shfl_xor_sync(0xffffffffu, z[1], 16);
                float th1 = z[3] + __shfl_xor_sync(0xffffffffu, z[3], 16);
                f0 = (lane & 16) ? th0 : tl0;
                f1 = (lane & 16) ? th1 : tl1;
            }
        }

        // epilogue: h_new = tanh(Wx + Uh) for my 2 outputs (dE, bE0/bE0+1)
        {
            float* hdst = hout + ((size_t)(t+1)*8 + s)*8192;
            float hn0 = tanhf(wxp0 + f0);
            float hn1 = tanhf(wxp1 + f1);
            sH[(bE0    )*SH_STRIDE + dE] = hn0;
            sH[(bE0 + 1)*SH_STRIDE + dE] = hn1;
            hdst[(bE0    )*1024 + dlo + dE] = hn0;
            hdst[(bE0 + 1)*1024 + dlo + dE] = hn1;
        }
    }
}

// ============== kernel 3: out = (sum_s C_s h[t+1,s]) * silu(z) ==============
__global__ __launch_bounds__(256) void out_kernel(const float* __restrict__ z,
                                                  const float* __restrict__ C,
                                                  const float* __restrict__ hout,
                                                  float* __restrict__ out) {
    size_t idx = (size_t)blockIdx.x * 256 + threadIdx.x;   // < T*B*D exactly
    int t   = (int)(idx >> 13);
    int rem = (int)(idx & 8191);
    float zz  = z[idx];
    float sig = 1.f / (1.f + expf(-zz));
    const float* hb = hout + ((size_t)(t+1))*65536 + rem;
    float acc = 0.f;
    #pragma unroll
    for (int s = 0; s < 8; s++) acc += C[s] * hb[(size_t)s*8192];
    out[idx] = acc * zz * sig;
}

// ================================ launch ================================
extern "C" void kernel_launch(void* const* d_in, const int* in_sizes, int n_in,
                              void* d_out, int out_size) {
    (void)in_sizes; (void)n_in; (void)out_size;
    const float* x    = (const float*)d_in[0];
    const float* z    = (const float*)d_in[1];
    const float* h0   = (const float*)d_in[2];
    const float* Wxm  = (const float*)d_in[3];
    const float* U    = (const float*)d_in[4];
    const float* V    = (const float*)d_in[5];
    const float* bias = (const float*)d_in[6];
    const float* C    = (const float*)d_in[7];

    float* out  = (float*)d_out;
    float* hout = out + (size_t)T_STEPS*BATCH*DIM;   // h region: [T+1][S][B][D]

    cudaFuncSetAttribute(recur_kernel_t<true>,
                         cudaFuncAttributeMaxDynamicSharedMemorySize, SMEM_BYTES);
    cudaFuncSetAttribute(recur_kernel_t<true>,
                         cudaFuncAttributeNonPortableClusterSizeAllowed, 1);
    cudaFuncSetAttribute(recur_kernel_t<false>,
                         cudaFuncAttributeMaxDynamicSharedMemorySize, SMEM_BYTES);

    dim3 wgrid(16, 128);                 // 64x64 tiles (R9 proven)
    wx_kernel<<<wgrid, 256>>>(x, Wxm, bias);

    // cluster launch config: 8 clusters x 16 CTAs (slot group == cluster)
    cudaLaunchConfig_t cfg = {};
    cfg.gridDim          = dim3(NCTAS, 1, 1);
    cfg.blockDim         = dim3(256, 1, 1);
    cfg.dynamicSmemBytes = SMEM_BYTES;
    cudaLaunchAttribute attrs[1];
    attrs[0].id = cudaLaunchAttributeClusterDimension;
    attrs[0].val.clusterDim.x = GROUP;
    attrs[0].val.clusterDim.y = 1;
    attrs[0].val.clusterDim.z = 1;
    cfg.attrs    = attrs;
    cfg.numAttrs = 1;

    int maxClusters = 0;
    cudaError_t qe = cudaOccupancyMaxActiveClusters(&maxClusters,
                                                    recur_kernel_t<true>, &cfg);
    bool use_cluster = (qe == cudaSuccess && maxClusters >= NSLOTS);
    if (!use_cluster) (void)cudaGetLastError();

    if (use_cluster) {
        cudaError_t le = cudaLaunchKernelEx(&cfg, recur_kernel_t<true>,
                                            h0, U, V, hout);
        if (le != cudaSuccess) {
            (void)cudaGetLastError();
            use_cluster = false;
        }
    }
    if (!use_cluster) {
        recur_kernel_t<false><<<NCTAS, 256, SMEM_BYTES>>>(h0, U, V, hout);
    }

    out_kernel<<<32768, 256>>>(z, C, hout, out);
}

// round 13
// speedup vs baseline: 1.0162x; 1.0162x over previous
#include <cuda_runtime.h>
#include <cstdint>
#include <cstddef>

#define T_STEPS 1024
#define BATCH   8
#define DIM     1024
#define NSLOTS  8
#define RANK    256
#define GROUP   16            // CTAs per slot group (= cluster size)
#define NCTAS   (NSLOTS*GROUP)

// SMEM strides (floats): odd multiples of 4 floats (16B) => 16B-aligned rows
// AND conflict-free LDS.128 column access.
#define SV_STRIDE  68          // V chunk: [256 r][64 d]   (17 float4)
#define SU_STRIDE  260         // U chunk: [64 d][256 r]   (65 float4)
#define SH_STRIDE  68          // own h:   [8 b][64 d]
#define SVH_STRIDE 260         // full Vh: [8 b][256 r]

#define SV_ELEMS   (256*SV_STRIDE)   // 17408
#define SU_ELEMS   (64*SU_STRIDE)    // 16640
#define SH_ELEMS   (8*SH_STRIDE)     // 544
#define SVH_ELEMS  (8*SVH_STRIDE)    // 2080
#define SRED_ELEMS 4096
#define SMEM_FLOATS (SV_ELEMS+SU_ELEMS+SH_ELEMS+SVH_ELEMS+SRED_ELEMS)
#define SMEM_BYTES  (SMEM_FLOATS*4)  // 163072 B < 227KB

// ---------------- device scratch (static, allocation-rule-safe) ----------------
__device__ float    g_wx[(size_t)T_STEPS*BATCH*DIM];   // Wx + bias, [t][b][d]
__device__ float    g_vh3[3*NSLOTS*BATCH*RANK];        // triple-buffered Vh accum [buf][s][b][r]
__device__ unsigned g_bar[NSLOTS];                     // fallback-path barrier

// packed fp32x2 FMA (full-rate fp32 on sm_103a; 3-reg FFMA is half rate)
__device__ __forceinline__ float2 ffma2(float2 a, float2 b, float2 c) {
    float2 d;
    asm("fma.rn.f32x2 %0, %1, %2, %3;"
        : "=l"(*reinterpret_cast<unsigned long long*>(&d))
        : "l"(*reinterpret_cast<const unsigned long long*>(&a)),
          "l"(*reinterpret_cast<const unsigned long long*>(&b)),
          "l"(*reinterpret_cast<const unsigned long long*>(&c)));
    return d;
}
__device__ __forceinline__ float2 lo2(float4 v) { return make_float2(v.x, v.y); }
__device__ __forceinline__ float2 hi2(float4 v) { return make_float2(v.z, v.w); }

// ======================= kernel 1: Wx = x @ W^T + bias =======================
// (proven version: 64x64 tiles, BK=32, 256 threads, 4x4/thread, ~437us)
__global__ __launch_bounds__(256) void wx_kernel(const float* __restrict__ x,
                                                 const float* __restrict__ W,
                                                 const float* __restrict__ bias) {
    __shared__ float sA[64*36];
    __shared__ float sB[64*36];
    const int tid = threadIdx.x;
    const int m0 = blockIdx.y * 64;
    const int n0 = blockIdx.x * 64;
    if (blockIdx.x == 0 && blockIdx.y == 0 && tid < NSLOTS) g_bar[tid] = 0u;
    if (blockIdx.y == 0) {                // 16 CTAs x 256 thr zero the Vh buffers
        int base = blockIdx.x * 256 + tid;
        #pragma unroll
        for (int k = 0; k < 12; k++) g_vh3[base + k*4096] = 0.f;
    }

    const int tm = tid >> 4;
    const int tn = tid & 15;

    float2 acc[4][4];
    #pragma unroll
    for (int i = 0; i < 4; i++)
        #pragma unroll
        for (int j = 0; j < 4; j++) acc[i][j] = make_float2(0.f, 0.f);

    for (int kb = 0; kb < 1024; kb += 32) {
        __syncthreads();
        #pragma unroll
        for (int it = 0; it < 2; it++) {
            int i = tid + it*256;
            int row = i >> 3, c4 = (i & 7) * 4;
            *(float4*)&sA[row*36 + c4] = *(const float4*)&x[(size_t)(m0+row)*1024 + kb + c4];
            *(float4*)&sB[row*36 + c4] = *(const float4*)&W[(size_t)(n0+row)*1024 + kb + c4];
        }
        __syncthreads();
        #pragma unroll
        for (int kk = 0; kk < 32; kk += 4) {
            float4 a[4], b[4];
            #pragma unroll
            for (int i = 0; i < 4; i++) a[i] = *(float4*)&sA[(tm+16*i)*36 + kk];
            #pragma unroll
            for (int j = 0; j < 4; j++) b[j] = *(float4*)&sB[(tn+16*j)*36 + kk];
            #pragma unroll
            for (int i = 0; i < 4; i++)
                #pragma unroll
                for (int j = 0; j < 4; j++) {
                    acc[i][j] = ffma2(lo2(a[i]), lo2(b[j]), acc[i][j]);
                    acc[i][j] = ffma2(hi2(a[i]), hi2(b[j]), acc[i][j]);
                }
        }
    }
    #pragma unroll
    for (int i = 0; i < 4; i++) {
        int m = m0 + tm + 16*i;
        #pragma unroll
        for (int j = 0; j < 4; j++) {
            int n = n0 + tn + 16*j;
            g_wx[(size_t)m*1024 + n] = acc[i][j].x + acc[i][j].y + bias[n];
        }
    }
}

// ================== kernel 2: persistent recurrence (d-partitioned) ==================
// 128 CTAs = 8 slots x 16 d-chunks, 256 threads. Same as R9 (4435us) except:
//  (1) GEMM1 partials REDG straight to L2 (no sRed combine, no post-GEMM1 sync)
//  (2) Vh staging is warp-local (warp w loads exactly the r-slice its GEMM2 reads)
//      -> post-stage __syncthreads becomes __syncwarp.
template <bool USE_CLUSTER>
__global__ void __launch_bounds__(256, 1)
recur_kernel_t(const float* __restrict__ h0, const float* __restrict__ U,
               const float* __restrict__ V, float* __restrict__ hout) {
    extern __shared__ float sm[];
    float* sV   = sm;                    // [256][SV_STRIDE]  V[s][r][dlo+dd]
    float* sU   = sV  + SV_ELEMS;        // [64][SU_STRIDE]   U[s][dlo+di][r]
    float* sH   = sU  + SU_ELEMS;        // [8][SH_STRIDE]    own h[b][dlo+dd]
    float* sVh  = sH  + SH_ELEMS;        // [8][SVH_STRIDE]   summed Vh[b][r]
    float* sRed = sVh + SVH_ELEMS;       // 4096 floats scratch (GEMM2 k-split)

    const int tid  = threadIdx.x;
    const int lane = tid & 31;
    const int w    = tid >> 5;
    const int s    = blockIdx.x >> 4;
    const int rk   = blockIdx.x & 15;
    const int dlo  = rk * 64;

    // resident weights (float4)
    #pragma unroll
    for (int k = 0; k < 16; k++) {          // V chunk (256 rows x 16 f4)
        int i = tid + k*256;
        int row = i >> 4, c4 = (i & 15) * 4;
        *(float4*)&sV[row*SV_STRIDE + c4] =
            *(const float4*)&V[((size_t)(s*256 + row))*1024 + dlo + c4];
    }
    #pragma unroll
    for (int k = 0; k < 16; k++) {          // U chunk (64 rows x 64 f4)
        int i = tid + k*256;
        int row = i >> 6, c4 = (i & 63) * 4;
        *(float4*)&sU[row*SU_STRIDE + c4] =
            *(const float4*)&U[((size_t)(s*1024 + dlo + row))*256 + c4];
    }
    // own h0 slice -> sH, and publish h[0] to output
    for (int i = tid; i < 512; i += 256) {
        int b = i >> 6, dd = i & 63;
        float v = h0[(size_t)b*8192 + s*1024 + dlo + dd];
        sH[b*SH_STRIDE + dd] = v;
        hout[(size_t)s*8192 + b*1024 + dlo + dd] = v;
    }

    // GEMM1 map: 128 r-threads (r, r+128) x 2 d-halves of 32
    const int rt1 = tid & 127;
    const int dbase1 = (tid >> 7) * 32;
    // GEMM2 map: 32 d-threads (d, d+32) x 8 r-slices of 32 (slice = warp id)
    const int dt2 = tid & 31;
    const int ks2 = tid >> 5;
    // staging map: warp w stages r-slice [32w, 32w+32): 2 float4 per lane
    const int stb = lane >> 2;           // b: 0..7
    const int stq = lane & 3;            // quad within slice
    // epilogue map
    const int edi = tid & 63;
    const int eb  = tid >> 6;            // handles b=eb and b=eb+4

    for (int t = 0; t < T_STEPS; t++) {
        // prefetch this step's Wx values (hides L2/DRAM latency behind GEMM1)
        const float* wxrow = g_wx + (size_t)t * 8192;
        float wxp0 = wxrow[(eb    )*1024 + dlo + edi];
        float wxp1 = wxrow[(eb + 4)*1024 + dlo + edi];

        __syncthreads();   // sH ready from previous iteration's epilogue

        float* gbuf = g_vh3 + ((size_t)(t % 3) * NSLOTS + s) * 2048;

        // ---- GEMM1: partial Vh[r][b] over own d-chunk; REDG partials directly ----
        {
            float2 acc[2][8];
            #pragma unroll
            for (int i = 0; i < 2; i++)
                #pragma unroll
                for (int b = 0; b < 8; b++) acc[i][b] = make_float2(0.f, 0.f);
            #pragma unroll
            for (int dd = 0; dd < 32; dd += 4) {
                int d = dbase1 + dd;
                float4 v0 = *(float4*)&sV[rt1*SV_STRIDE + d];
                float4 v1 = *(float4*)&sV[(rt1+128)*SV_STRIDE + d];
                #pragma unroll
                for (int b = 0; b < 8; b++) {
                    float4 hh = *(float4*)&sH[b*SH_STRIDE + d];   // broadcast
                    acc[0][b] = ffma2(lo2(v0), lo2(hh), acc[0][b]);
                    acc[0][b] = ffma2(hi2(v0), hi2(hh), acc[0][b]);
                    acc[1][b] = ffma2(lo2(v1), lo2(hh), acc[1][b]);
                    acc[1][b] = ffma2(hi2(v1), hi2(hh), acc[1][b]);
                }
            }
            // fire-and-forget REDG: L2 does the cross-CTA (and cross-d-half) sum
            #pragma unroll
            for (int b = 0; b < 8; b++) {
                atomicAdd(&gbuf[b*256 + rt1      ], acc[0][b].x + acc[0][b].y);
                atomicAdd(&gbuf[b*256 + rt1 + 128], acc[1][b].x + acc[1][b].y);
            }
        }
        // (no __syncthreads: each thread's REDs are ordered by its own barrier arrive)

        // ---- ONE barrier per step (per slot group) ----
        if (USE_CLUSTER) {
            // arrive = cluster-scope release (orders the REDs above);
            // wait   = cluster-scope acquire (orders the ldcg reads below).
            asm volatile("barrier.cluster.arrive.aligned;" ::: "memory");
            asm volatile("barrier.cluster.wait.aligned;"   ::: "memory");
        } else {
            __threadfence();
            __syncthreads();
            if (tid == 0) {
                atomicAdd(&g_bar[s], 1u);
                unsigned target = (unsigned)GROUP * (unsigned)(t + 1);
                while (*((volatile unsigned*)&g_bar[s]) < target) { }
            }
            __syncthreads();
        }

        // stage summed Vh WARP-LOCALLY: warp w loads r-slice [32w,32w+32) for all b
        // (exactly the slice GEMM2 warp w reads) -> only __syncwarp needed.
        {
            const float4* src = (const float4*)gbuf;   // [b][64 f4]
            int f = stb*64 + w*8 + stq*2;
            float4 v0 = __ldcg(&src[f]);
            float4 v1 = __ldcg(&src[f+1]);
            *(float4*)&sVh[stb*SVH_STRIDE + (w*8 + stq*2)*4    ] = v0;
            *(float4*)&sVh[stb*SVH_STRIDE + (w*8 + stq*2)*4 + 4] = v1;
            // zero the buffer for step t+2 (ordered by the t+1 barrier)
            float* zbuf = g_vh3 + ((size_t)((t + 2) % 3) * NSLOTS + s) * 2048;
            if (tid < 128) zbuf[rk*128 + tid] = 0.f;
            __syncwarp();
        }

        // ---- GEMM2: Uh[d][b] = sum_r U[d][r]*Vh[b][r] (float4 over r) ----
        {
            float2 acc[2][8];
            #pragma unroll
            for (int i = 0; i < 2; i++)
                #pragma unroll
                for (int b = 0; b < 8; b++) acc[i][b] = make_float2(0.f, 0.f);
            const int rbase = ks2 * 32;
            #pragma unroll
            for (int rr = 0; rr < 32; rr += 4) {
                int r = rbase + rr;
                float4 u0 = *(float4*)&sU[dt2*SU_STRIDE + r];
                float4 u1 = *(float4*)&sU[(dt2+32)*SU_STRIDE + r];
                #pragma unroll
                for (int b = 0; b < 8; b++) {
                    float4 vh = *(float4*)&sVh[b*SVH_STRIDE + r];  // broadcast
                    acc[0][b] = ffma2(lo2(u0), lo2(vh), acc[0][b]);
                    acc[0][b] = ffma2(hi2(u0), hi2(vh), acc[0][b]);
                    acc[1][b] = ffma2(lo2(u1), lo2(vh), acc[1][b]);
                    acc[1][b] = ffma2(hi2(u1), hi2(vh), acc[1][b]);
                }
            }
            #pragma unroll
            for (int i = 0; i < 2; i++)
                #pragma unroll
                for (int b = 0; b < 8; b++)
                    sRed[ks2*512 + b*64 + dt2 + 32*i] = acc[i][b].x + acc[i][b].y;
        }
        __syncthreads();

        // epilogue: h_new = tanh(Wx + Uh); keep slice in sH, publish to hout
        {
            float* hdst = hout + ((size_t)(t+1)*8 + s)*8192;
            #pragma unroll
            for (int j = 0; j < 2; j++) {
                int b = eb + 4*j;
                float uh = 0.f;
                #pragma unroll
                for (int k = 0; k < 8; k++) uh += sRed[k*512 + b*64 + edi];
                float hn = tanhf((j == 0 ? wxp0 : wxp1) + uh);
                sH[b*SH_STRIDE + edi] = hn;
                hdst[b*1024 + dlo + edi] = hn;
            }
        }
    }
}

// ============== kernel 3: out = (sum_s C_s h[t+1,s]) * silu(z) ==============
__global__ __launch_bounds__(256) void out_kernel(const float* __restrict__ z,
                                                  const float* __restrict__ C,
                                                  const float* __restrict__ hout,
                                                  float* __restrict__ out) {
    size_t idx = (size_t)blockIdx.x * 256 + threadIdx.x;   // < T*B*D exactly
    int t   = (int)(idx >> 13);
    int rem = (int)(idx & 8191);
    float zz  = z[idx];
    float sig = 1.f / (1.f + expf(-zz));
    const float* hb = hout + ((size_t)(t+1))*65536 + rem;
    float acc = 0.f;
    #pragma unroll
    for (int s = 0; s < 8; s++) acc += C[s] * hb[(size_t)s*8192];
    out[idx] = acc * zz * sig;
}

// ================================ launch ================================
extern "C" void kernel_launch(void* const* d_in, const int* in_sizes, int n_in,
                              void* d_out, int out_size) {
    (void)in_sizes; (void)n_in; (void)out_size;
    const float* x    = (const float*)d_in[0];
    const float* z    = (const float*)d_in[1];
    const float* h0   = (const float*)d_in[2];
    const float* Wxm  = (const float*)d_in[3];
    const float* U    = (const float*)d_in[4];
    const float* V    = (const float*)d_in[5];
    const float* bias = (const float*)d_in[6];
    const float* C    = (const float*)d_in[7];

    float* out  = (float*)d_out;
    float* hout = out + (size_t)T_STEPS*BATCH*DIM;   // h region: [T+1][S][B][D]

    cudaFuncSetAttribute(recur_kernel_t<true>,
                         cudaFuncAttributeMaxDynamicSharedMemorySize, SMEM_BYTES);
    cudaFuncSetAttribute(recur_kernel_t<true>,
                         cudaFuncAttributeNonPortableClusterSizeAllowed, 1);
    cudaFuncSetAttribute(recur_kernel_t<false>,
                         cudaFuncAttributeMaxDynamicSharedMemorySize, SMEM_BYTES);

    dim3 wgrid(16, 128);
    wx_kernel<<<wgrid, 256>>>(x, Wxm, bias);

    // cluster launch config: 8 clusters x 16 CTAs (slot group == cluster)
    cudaLaunchConfig_t cfg = {};
    cfg.gridDim          = dim3(NCTAS, 1, 1);
    cfg.blockDim         = dim3(256, 1, 1);
    cfg.dynamicSmemBytes = SMEM_BYTES;
    cudaLaunchAttribute attrs[1];
    attrs[0].id = cudaLaunchAttributeClusterDimension;
    attrs[0].val.clusterDim.x = GROUP;
    attrs[0].val.clusterDim.y = 1;
    attrs[0].val.clusterDim.z = 1;
    cfg.attrs    = attrs;
    cfg.numAttrs = 1;

    int maxClusters = 0;
    cudaError_t qe = cudaOccupancyMaxActiveClusters(&maxClusters,
                                                    recur_kernel_t<true>, &cfg);
    bool use_cluster = (qe == cudaSuccess && maxClusters >= NSLOTS);
    if (!use_cluster) (void)cudaGetLastError();

    if (use_cluster) {
        cudaError_t le = cudaLaunchKernelEx(&cfg, recur_kernel_t<true>,
                                            h0, U, V, hout);
        if (le != cudaSuccess) {
            (void)cudaGetLastError();
            use_cluster = false;
        }
    }
    if (!use_cluster) {
        recur_kernel_t<false><<<NCTAS, 256, SMEM_BYTES>>>(h0, U, V, hout);
    }

    out_kernel<<<32768, 256>>>(z, C, hout, out);
}

// round 14
// speedup vs baseline: 1.0522x; 1.0355x over previous
#include <cuda_runtime.h>
#include <cstdint>
#include <cstddef>

#define T_STEPS 1024
#define BATCH   8
#define DIM     1024
#define NSLOTS  8
#define RANK    256
#define GROUP   16            // CTAs per slot group (= cluster size)
#define NCTAS   (NSLOTS*GROUP)

// SMEM strides (floats): odd multiples of 4 floats (16B) => 16B-aligned rows
// AND conflict-free LDS.128 column access.
#define SV_STRIDE  68          // V chunk: [256 r][64 d]   (17 float4)
#define SU_STRIDE  260         // U chunk: [64 d][256 r]   (65 float4)
#define SH_STRIDE  68          // own h:   [8 b][64 d]
#define SVH_STRIDE 260         // full Vh: [8 b][256 r]

#define SV_ELEMS   (256*SV_STRIDE)   // 17408
#define SU_ELEMS   (64*SU_STRIDE)    // 16640
#define SH_ELEMS   (8*SH_STRIDE)     // 544
#define SVH_ELEMS  (8*SVH_STRIDE)    // 2080
#define SRED_ELEMS 4096              // GEMM2 k-split scratch only
#define SMEM_FLOATS (SV_ELEMS+SU_ELEMS+SH_ELEMS+SVH_ELEMS+SRED_ELEMS)
#define SMEM_BYTES  (SMEM_FLOATS*4)  // 163072 B < 227KB

// ---------------- device scratch (static, allocation-rule-safe) ----------------
__device__ float    g_wx[(size_t)T_STEPS*BATCH*DIM];   // Wx + bias, [t][b][d]
__device__ float    g_vh3[3*NSLOTS*BATCH*RANK];        // triple-buffered Vh accum [buf][s][b][r]
__device__ unsigned g_bar[NSLOTS];                     // fallback-path barrier

// packed fp32x2 FMA (full-rate fp32 on sm_103a; 3-reg FFMA is half rate)
__device__ __forceinline__ float2 ffma2(float2 a, float2 b, float2 c) {
    float2 d;
    asm("fma.rn.f32x2 %0, %1, %2, %3;"
        : "=l"(*reinterpret_cast<unsigned long long*>(&d))
        : "l"(*reinterpret_cast<const unsigned long long*>(&a)),
          "l"(*reinterpret_cast<const unsigned long long*>(&b)),
          "l"(*reinterpret_cast<const unsigned long long*>(&c)));
    return d;
}
__device__ __forceinline__ float2 lo2(float4 v) { return make_float2(v.x, v.y); }
__device__ __forceinline__ float2 hi2(float4 v) { return make_float2(v.z, v.w); }

// ======================= kernel 1: Wx = x @ W^T + bias =======================
// (proven version: 64x64 tiles, BK=32, 256 threads, 4x4/thread, ~437us)
__global__ __launch_bounds__(256) void wx_kernel(const float* __restrict__ x,
                                                 const float* __restrict__ W,
                                                 const float* __restrict__ bias) {
    __shared__ float sA[64*36];
    __shared__ float sB[64*36];
    const int tid = threadIdx.x;
    const int m0 = blockIdx.y * 64;
    const int n0 = blockIdx.x * 64;
    if (blockIdx.x == 0 && blockIdx.y == 0 && tid < NSLOTS) g_bar[tid] = 0u;
    if (blockIdx.y == 0) {                // 16 CTAs x 256 thr zero the Vh buffers
        int base = blockIdx.x * 256 + tid;
        #pragma unroll
        for (int k = 0; k < 12; k++) g_vh3[base + k*4096] = 0.f;
    }

    const int tm = tid >> 4;
    const int tn = tid & 15;

    float2 acc[4][4];
    #pragma unroll
    for (int i = 0; i < 4; i++)
        #pragma unroll
        for (int j = 0; j < 4; j++) acc[i][j] = make_float2(0.f, 0.f);

    for (int kb = 0; kb < 1024; kb += 32) {
        __syncthreads();
        #pragma unroll
        for (int it = 0; it < 2; it++) {
            int i = tid + it*256;
            int row = i >> 3, c4 = (i & 7) * 4;
            *(float4*)&sA[row*36 + c4] = *(const float4*)&x[(size_t)(m0+row)*1024 + kb + c4];
            *(float4*)&sB[row*36 + c4] = *(const float4*)&W[(size_t)(n0+row)*1024 + kb + c4];
        }
        __syncthreads();
        #pragma unroll
        for (int kk = 0; kk < 32; kk += 4) {
            float4 a[4], b[4];
            #pragma unroll
            for (int i = 0; i < 4; i++) a[i] = *(float4*)&sA[(tm+16*i)*36 + kk];
            #pragma unroll
            for (int j = 0; j < 4; j++) b[j] = *(float4*)&sB[(tn+16*j)*36 + kk];
            #pragma unroll
            for (int i = 0; i < 4; i++)
                #pragma unroll
                for (int j = 0; j < 4; j++) {
                    acc[i][j] = ffma2(lo2(a[i]), lo2(b[j]), acc[i][j]);
                    acc[i][j] = ffma2(hi2(a[i]), hi2(b[j]), acc[i][j]);
                }
        }
    }
    #pragma unroll
    for (int i = 0; i < 4; i++) {
        int m = m0 + tm + 16*i;
        #pragma unroll
        for (int j = 0; j < 4; j++) {
            int n = n0 + tn + 16*j;
            g_wx[(size_t)m*1024 + n] = acc[i][j].x + acc[i][j].y + bias[n];
        }
    }
}

// ================== kernel 2: persistent recurrence (d-partitioned) ==================
// 128 CTAs = 8 slots x 16 d-chunks, 256 threads. R9 structure with:
//  (1) GEMM1 d-split INTRA-warp (lane<16 vs >=16); one shfl_xor(16) round combines;
//      each thread REDGs its 8 FINAL (b,r) values -> 2048 REDs/CTA (same as R9),
//      no post-GEMM1 __syncthreads, no sRed round trip for GEMM1.
//  (2) Vh staging warp-local (warp w loads exactly r-slice [32w,32w+32) that its
//      GEMM2 slice reads) -> __syncwarp instead of __syncthreads.
template <bool USE_CLUSTER>
__global__ void __launch_bounds__(256, 1)
recur_kernel_t(const float* __restrict__ h0, const float* __restrict__ U,
               const float* __restrict__ V, float* __restrict__ hout) {
    extern __shared__ float sm[];
    float* sV   = sm;                    // [256][SV_STRIDE]  V[s][r][dlo+dd]
    float* sU   = sV  + SV_ELEMS;        // [64][SU_STRIDE]   U[s][dlo+di][r]
    float* sH   = sU  + SU_ELEMS;        // [8][SH_STRIDE]    own h[b][dlo+dd]
    float* sVh  = sH  + SH_ELEMS;        // [8][SVH_STRIDE]   summed Vh[b][r]
    float* sRed = sVh + SVH_ELEMS;       // 4096 floats scratch (GEMM2 only)

    const int tid  = threadIdx.x;
    const int lane = tid & 31;
    const int w    = tid >> 5;
    const int s    = blockIdx.x >> 4;
    const int rk   = blockIdx.x & 15;
    const int dlo  = rk * 64;

    // resident weights (float4)
    #pragma unroll
    for (int k = 0; k < 16; k++) {          // V chunk (256 rows x 16 f4)
        int i = tid + k*256;
        int row = i >> 4, c4 = (i & 15) * 4;
        *(float4*)&sV[row*SV_STRIDE + c4] =
            *(const float4*)&V[((size_t)(s*256 + row))*1024 + dlo + c4];
    }
    #pragma unroll
    for (int k = 0; k < 16; k++) {          // U chunk (64 rows x 64 f4)
        int i = tid + k*256;
        int row = i >> 6, c4 = (i & 63) * 4;
        *(float4*)&sU[row*SU_STRIDE + c4] =
            *(const float4*)&U[((size_t)(s*1024 + dlo + row))*256 + c4];
    }
    // own h0 slice -> sH, and publish h[0] to output
    for (int i = tid; i < 512; i += 256) {
        int b = i >> 6, dd = i & 63;
        float v = h0[(size_t)b*8192 + s*1024 + dlo + dd];
        sH[b*SH_STRIDE + dd] = v;
        hout[(size_t)s*8192 + b*1024 + dlo + dd] = v;
    }

    // GEMM1 map (intra-warp d-split): warp w covers r = 16w+(lane&15) and +128.
    const int rA  = w*16 + (lane & 15);
    const int db1 = (lane >> 4) * 32;      // my d-half
    const int rPub = (lane < 16) ? rA : (rA + 128);   // r I publish after shfl
    // GEMM2 map: 32 d-threads (d, d+32) x 8 r-slices of 32 (slice = warp id)
    const int dt2 = tid & 31;
    const int ks2 = tid >> 5;
    // staging map: warp w stages r-slice [32w, 32w+32): 2 float4 per lane
    const int stb = lane >> 2;             // b: 0..7
    const int stq = lane & 3;              // quad within slice
    // epilogue map
    const int edi = tid & 63;
    const int eb  = tid >> 6;              // handles b=eb and b=eb+4

    for (int t = 0; t < T_STEPS; t++) {
        // prefetch this step's Wx values (hides L2/DRAM latency behind GEMM1)
        const float* wxrow = g_wx + (size_t)t * 8192;
        float wxp0 = wxrow[(eb    )*1024 + dlo + edi];
        float wxp1 = wxrow[(eb + 4)*1024 + dlo + edi];

        __syncthreads();   // sH ready from previous iteration's epilogue

        float* gbuf = g_vh3 + ((size_t)(t % 3) * NSLOTS + s) * 2048;

        // ---- GEMM1: partial Vh[r][b] over own d-chunk, intra-warp d-split ----
        {
            float2 acc[2][8];   // [ri][b], ri: 0 = rA, 1 = rA+128
            #pragma unroll
            for (int i = 0; i < 2; i++)
                #pragma unroll
                for (int b = 0; b < 8; b++) acc[i][b] = make_float2(0.f, 0.f);
            #pragma unroll
            for (int dd = 0; dd < 32; dd += 4) {
                int d = db1 + dd;
                float4 v0 = *(float4*)&sV[rA*SV_STRIDE + d];
                float4 v1 = *(float4*)&sV[(rA+128)*SV_STRIDE + d];
                #pragma unroll
                for (int b = 0; b < 8; b++) {
                    float4 hh = *(float4*)&sH[b*SH_STRIDE + d];   // broadcast
                    acc[0][b] = ffma2(lo2(v0), lo2(hh), acc[0][b]);
                    acc[0][b] = ffma2(hi2(v0), hi2(hh), acc[0][b]);
                    acc[1][b] = ffma2(lo2(v1), lo2(hh), acc[1][b]);
                    acc[1][b] = ffma2(hi2(v1), hi2(hh), acc[1][b]);
                }
            }
            // combine d-halves with ONE shfl round; publish final 8 values via REDG
            float xs[16];
            #pragma unroll
            for (int i = 0; i < 2; i++)
                #pragma unroll
                for (int b = 0; b < 8; b++) xs[i*8+b] = acc[i][b].x + acc[i][b].y;
            #pragma unroll
            for (int i = 0; i < 16; i++)
                xs[i] += __shfl_xor_sync(0xffffffffu, xs[i], 16);
            #pragma unroll
            for (int b = 0; b < 8; b++) {
                float v = (lane < 16) ? xs[b] : xs[8+b];
                atomicAdd(&gbuf[b*256 + rPub], v);   // REDG, 2048/CTA (as R9)
            }
        }
        // (no __syncthreads: barrier arrive below releases each thread's own REDs)

        // ---- ONE barrier per step (per slot group) ----
        if (USE_CLUSTER) {
            asm volatile("barrier.cluster.arrive.aligned;" ::: "memory");
            asm volatile("barrier.cluster.wait.aligned;"   ::: "memory");
        } else {
            __threadfence();
            __syncthreads();
            if (tid == 0) {
                atomicAdd(&g_bar[s], 1u);
                unsigned target = (unsigned)GROUP * (unsigned)(t + 1);
                while (*((volatile unsigned*)&g_bar[s]) < target) { }
            }
            __syncthreads();
        }

        // stage summed Vh WARP-LOCALLY: warp w loads r-slice [32w,32w+32) for all b
        // (exactly the slice its GEMM2 reads) -> __syncwarp suffices.
        {
            const float4* src = (const float4*)gbuf;   // [b][64 f4]
            int f = stb*64 + w*8 + stq*2;
            float4 v0 = __ldcg(&src[f]);
            float4 v1 = __ldcg(&src[f+1]);
            *(float4*)&sVh[stb*SVH_STRIDE + (w*8 + stq*2)*4    ] = v0;
            *(float4*)&sVh[stb*SVH_STRIDE + (w*8 + stq*2)*4 + 4] = v1;
            // zero the buffer for step t+2 (ordered by the t+1 barrier)
            float* zbuf = g_vh3 + ((size_t)((t + 2) % 3) * NSLOTS + s) * 2048;
            if (tid < 128) zbuf[rk*128 + tid] = 0.f;
            __syncwarp();
        }

        // ---- GEMM2: Uh[d][b] = sum_r U[d][r]*Vh[b][r] (float4 over r) ----
        {
            float2 acc[2][8];
            #pragma unroll
            for (int i = 0; i < 2; i++)
                #pragma unroll
                for (int b = 0; b < 8; b++) acc[i][b] = make_float2(0.f, 0.f);
            const int rbase = ks2 * 32;
            #pragma unroll
            for (int rr = 0; rr < 32; rr += 4) {
                int r = rbase + rr;
                float4 u0 = *(float4*)&sU[dt2*SU_STRIDE + r];
                float4 u1 = *(float4*)&sU[(dt2+32)*SU_STRIDE + r];
                #pragma unroll
                for (int b = 0; b < 8; b++) {
                    float4 vh = *(float4*)&sVh[b*SVH_STRIDE + r];  // broadcast
                    acc[0][b] = ffma2(lo2(u0), lo2(vh), acc[0][b]);
                    acc[0][b] = ffma2(hi2(u0), hi2(vh), acc[0][b]);
                    acc[1][b] = ffma2(lo2(u1), lo2(vh), acc[1][b]);
                    acc[1][b] = ffma2(hi2(u1), hi2(vh), acc[1][b]);
                }
            }
            #pragma unroll
            for (int i = 0; i < 2; i++)
                #pragma unroll
                for (int b = 0; b < 8; b++)
                    sRed[ks2*512 + b*64 + dt2 + 32*i] = acc[i][b].x + acc[i][b].y;
        }
        __syncthreads();

        // epilogue: h_new = tanh(Wx + Uh); keep slice in sH, publish to hout
        {
            float* hdst = hout + ((size_t)(t+1)*8 + s)*8192;
            #pragma unroll
            for (int j = 0; j < 2; j++) {
                int b = eb + 4*j;
                float uh = 0.f;
                #pragma unroll
                for (int k = 0; k < 8; k++) uh += sRed[k*512 + b*64 + edi];
                float hn = tanhf((j == 0 ? wxp0 : wxp1) + uh);
                sH[b*SH_STRIDE + edi] = hn;
                hdst[b*1024 + dlo + edi] = hn;
            }
        }
    }
}

// ============== kernel 3: out = (sum_s C_s h[t+1,s]) * silu(z) ==============
__global__ __launch_bounds__(256) void out_kernel(const float* __restrict__ z,
                                                  const float* __restrict__ C,
                                                  const float* __restrict__ hout,
                                                  float* __restrict__ out) {
    size_t idx = (size_t)blockIdx.x * 256 + threadIdx.x;   // < T*B*D exactly
    int t   = (int)(idx >> 13);
    int rem = (int)(idx & 8191);
    float zz  = z[idx];
    float sig = 1.f / (1.f + expf(-zz));
    const float* hb = hout + ((size_t)(t+1))*65536 + rem;
    float acc = 0.f;
    #pragma unroll
    for (int s = 0; s < 8; s++) acc += C[s] * hb[(size_t)s*8192];
    out[idx] = acc * zz * sig;
}

// ================================ launch ================================
extern "C" void kernel_launch(void* const* d_in, const int* in_sizes, int n_in,
                              void* d_out, int out_size) {
    (void)in_sizes; (void)n_in; (void)out_size;
    const float* x    = (const float*)d_in[0];
    const float* z    = (const float*)d_in[1];
    const float* h0   = (const float*)d_in[2];
    const float* Wxm  = (const float*)d_in[3];
    const float* U    = (const float*)d_in[4];
    const float* V    = (const float*)d_in[5];
    const float* bias = (const float*)d_in[6];
    const float* C    = (const float*)d_in[7];

    float* out  = (float*)d_out;
    float* hout = out + (size_t)T_STEPS*BATCH*DIM;   // h region: [T+1][S][B][D]

    cudaFuncSetAttribute(recur_kernel_t<true>,
                         cudaFuncAttributeMaxDynamicSharedMemorySize, SMEM_BYTES);
    cudaFuncSetAttribute(recur_kernel_t<true>,
                         cudaFuncAttributeNonPortableClusterSizeAllowed, 1);
    cudaFuncSetAttribute(recur_kernel_t<false>,
                         cudaFuncAttributeMaxDynamicSharedMemorySize, SMEM_BYTES);

    dim3 wgrid(16, 128);
    wx_kernel<<<wgrid, 256>>>(x, Wxm, bias);

    // cluster launch config: 8 clusters x 16 CTAs (slot group == cluster)
    cudaLaunchConfig_t cfg = {};
    cfg.gridDim          = dim3(NCTAS, 1, 1);
    cfg.blockDim         = dim3(256, 1, 1);
    cfg.dynamicSmemBytes = SMEM_BYTES;
    cudaLaunchAttribute attrs[1];
    attrs[0].id = cudaLaunchAttributeClusterDimension;
    attrs[0].val.clusterDim.x = GROUP;
    attrs[0].val.clusterDim.y = 1;
    attrs[0].val.clusterDim.z = 1;
    cfg.attrs    = attrs;
    cfg.numAttrs = 1;

    int maxClusters = 0;
    cudaError_t qe = cudaOccupancyMaxActiveClusters(&maxClusters,
                                                    recur_kernel_t<true>, &cfg);
    bool use_cluster = (qe == cudaSuccess && maxClusters >= NSLOTS);
    if (!use_cluster) (void)cudaGetLastError();

    if (use_cluster) {
        cudaError_t le = cudaLaunchKernelEx(&cfg, recur_kernel_t<true>,
                                            h0, U, V, hout);
        if (le != cudaSuccess) {
            (void)cudaGetLastError();
            use_cluster = false;
        }
    }
    if (!use_cluster) {
        recur_kernel_t<false><<<NCTAS, 256, SMEM_BYTES>>>(h0, U, V, hout);
    }

    out_kernel<<<32768, 256>>>(z, C, hout, out);
}

// round 16
// speedup vs baseline: 1.0595x; 1.0069x over previous
#include <cuda_runtime.h>
#include <cstdint>
#include <cstddef>

#define T_STEPS 1024
#define BATCH   8
#define DIM     1024
#define NSLOTS  8
#define RANK    256
#define GROUP   16            // CTAs per slot group (= cluster size)
#define NCTAS   (NSLOTS*GROUP)

// SMEM strides (floats): odd multiples of 4 floats (16B) => 16B-aligned rows
// AND conflict-free LDS.128 column access.
#define SV_STRIDE  68          // V chunk: [256 r][64 d]   (17 float4)
#define SU_STRIDE  260         // U chunk: [64 d][256 r]   (65 float4)
#define SH_STRIDE  68          // own h:   [8 b][64 d]
#define SVH_STRIDE 260         // full Vh: [8 b][256 r]

#define SV_ELEMS   (256*SV_STRIDE)   // 17408
#define SU_ELEMS   (64*SU_STRIDE)    // 16640
#define SH_ELEMS   (8*SH_STRIDE)     // 544
#define SVH_ELEMS  (8*SVH_STRIDE)    // 2080
#define SRED_ELEMS 4096
#define SMEM_FLOATS (SV_ELEMS+SU_ELEMS+SH_ELEMS+SVH_ELEMS+SRED_ELEMS)
#define SMEM_BYTES  (SMEM_FLOATS*4)  // 163072 B < 227KB

// ---------------- device scratch (static, allocation-rule-safe) ----------------
__device__ float    g_wx[(size_t)T_STEPS*BATCH*DIM];   // Wx + bias, [t][b][d]
__device__ float    g_vh3[3*NSLOTS*BATCH*RANK];        // triple-buffered Vh accum [buf][s][b][r]
__device__ unsigned g_bar[NSLOTS];                     // fallback-path barrier

// packed fp32x2 FMA (full-rate fp32 on sm_103a; 3-reg FFMA is half rate)
__device__ __forceinline__ float2 ffma2(float2 a, float2 b, float2 c) {
    float2 d;
    asm("fma.rn.f32x2 %0, %1, %2, %3;"
        : "=l"(*reinterpret_cast<unsigned long long*>(&d))
        : "l"(*reinterpret_cast<const unsigned long long*>(&a)),
          "l"(*reinterpret_cast<const unsigned long long*>(&b)),
          "l"(*reinterpret_cast<const unsigned long long*>(&c)));
    return d;
}
__device__ __forceinline__ float2 lo2(float4 v) { return make_float2(v.x, v.y); }
__device__ __forceinline__ float2 hi2(float4 v) { return make_float2(v.z, v.w); }

// vectorized global reduction: one instruction adds 4 consecutive floats
__device__ __forceinline__ void red_add_v4(float* addr, float4 v) {
    asm volatile("red.global.add.v4.f32 [%0], {%1, %2, %3, %4};"
                 :: "l"(addr), "f"(v.x), "f"(v.y), "f"(v.z), "f"(v.w)
                 : "memory");
}

// ======================= kernel 1: Wx = x @ W^T + bias =======================
// (proven version: 64x64 tiles, BK=32, 256 threads, 4x4/thread, ~437us)
__global__ __launch_bounds__(256) void wx_kernel(const float* __restrict__ x,
                                                 const float* __restrict__ W,
                                                 const float* __restrict__ bias) {
    __shared__ float sA[64*36];
    __shared__ float sB[64*36];
    const int tid = threadIdx.x;
    const int m0 = blockIdx.y * 64;
    const int n0 = blockIdx.x * 64;
    if (blockIdx.x == 0 && blockIdx.y == 0 && tid < NSLOTS) g_bar[tid] = 0u;
    if (blockIdx.y == 0) {                // 16 CTAs x 256 thr zero the Vh buffers
        int base = blockIdx.x * 256 + tid;
        #pragma unroll
        for (int k = 0; k < 12; k++) g_vh3[base + k*4096] = 0.f;
    }

    const int tm = tid >> 4;
    const int tn = tid & 15;

    float2 acc[4][4];
    #pragma unroll
    for (int i = 0; i < 4; i++)
        #pragma unroll
        for (int j = 0; j < 4; j++) acc[i][j] = make_float2(0.f, 0.f);

    for (int kb = 0; kb < 1024; kb += 32) {
        __syncthreads();
        #pragma unroll
        for (int it = 0; it < 2; it++) {
            int i = tid + it*256;
            int row = i >> 3, c4 = (i & 7) * 4;
            *(float4*)&sA[row*36 + c4] = *(const float4*)&x[(size_t)(m0+row)*1024 + kb + c4];
            *(float4*)&sB[row*36 + c4] = *(const float4*)&W[(size_t)(n0+row)*1024 + kb + c4];
        }
        __syncthreads();
        #pragma unroll
        for (int kk = 0; kk < 32; kk += 4) {
            float4 a[4], b[4];
            #pragma unroll
            for (int i = 0; i < 4; i++) a[i] = *(float4*)&sA[(tm+16*i)*36 + kk];
            #pragma unroll
            for (int j = 0; j < 4; j++) b[j] = *(float4*)&sB[(tn+16*j)*36 + kk];
            #pragma unroll
            for (int i = 0; i < 4; i++)
                #pragma unroll
                for (int j = 0; j < 4; j++) {
                    acc[i][j] = ffma2(lo2(a[i]), lo2(b[j]), acc[i][j]);
                    acc[i][j] = ffma2(hi2(a[i]), hi2(b[j]), acc[i][j]);
                }
        }
    }
    #pragma unroll
    for (int i = 0; i < 4; i++) {
        int m = m0 + tm + 16*i;
        #pragma unroll
        for (int j = 0; j < 4; j++) {
            int n = n0 + tn + 16*j;
            g_wx[(size_t)m*1024 + n] = acc[i][j].x + acc[i][j].y + bias[n];
        }
    }
}

// ================== kernel 2: persistent recurrence (d-partitioned) ==================
// EXACT R9 structure (4435us best) with ONE change: the Vh publish uses
// red.global.add.v4.f32 (512 vector REDs/CTA) instead of 2048 scalar REDs.
template <bool USE_CLUSTER>
__global__ void __launch_bounds__(256, 1)
recur_kernel_t(const float* __restrict__ h0, const float* __restrict__ U,
               const float* __restrict__ V, float* __restrict__ hout) {
    extern __shared__ float sm[];
    float* sV   = sm;                    // [256][SV_STRIDE]  V[s][r][dlo+dd]
    float* sU   = sV  + SV_ELEMS;        // [64][SU_STRIDE]   U[s][dlo+di][r]
    float* sH   = sU  + SU_ELEMS;        // [8][SH_STRIDE]    own h[b][dlo+dd]
    float* sVh  = sH  + SH_ELEMS;        // [8][SVH_STRIDE]   summed Vh[b][r]
    float* sRed = sVh + SVH_ELEMS;       // 4096 floats scratch

    const int tid = threadIdx.x;
    const int s   = blockIdx.x >> 4;
    const int rk  = blockIdx.x & 15;
    const int dlo = rk * 64;

    // resident weights (float4)
    #pragma unroll
    for (int k = 0; k < 16; k++) {          // V chunk (256 rows x 16 f4)
        int i = tid + k*256;
        int row = i >> 4, c4 = (i & 15) * 4;
        *(float4*)&sV[row*SV_STRIDE + c4] =
            *(const float4*)&V[((size_t)(s*256 + row))*1024 + dlo + c4];
    }
    #pragma unroll
    for (int k = 0; k < 16; k++) {          // U chunk (64 rows x 64 f4)
        int i = tid + k*256;
        int row = i >> 6, c4 = (i & 63) * 4;
        *(float4*)&sU[row*SU_STRIDE + c4] =
            *(const float4*)&U[((size_t)(s*1024 + dlo + row))*256 + c4];
    }
    // own h0 slice -> sH, and publish h[0] to output
    for (int i = tid; i < 512; i += 256) {
        int b = i >> 6, dd = i & 63;
        float v = h0[(size_t)b*8192 + s*1024 + dlo + dd];
        sH[b*SH_STRIDE + dd] = v;
        hout[(size_t)s*8192 + b*1024 + dlo + dd] = v;
    }

    // GEMM1 map: 128 r-threads (r, r+128) x 2 d-halves of 32
    const int rt1 = tid & 127;
    const int dbase1 = (tid >> 7) * 32;
    const int ks1 = tid >> 7;
    // GEMM2 map: 32 d-threads (d, d+32) x 8 r-slices of 32
    const int dt2 = tid & 31;
    const int ks2 = tid >> 5;
    // epilogue map
    const int edi = tid & 63;
    const int eb  = tid >> 6;            // handles b=eb and b=eb+4

    for (int t = 0; t < T_STEPS; t++) {
        // prefetch this step's Wx values (hides L2/DRAM latency behind GEMM1)
        const float* wxrow = g_wx + (size_t)t * 8192;
        float wxp0 = wxrow[(eb    )*1024 + dlo + edi];
        float wxp1 = wxrow[(eb + 4)*1024 + dlo + edi];

        __syncthreads();   // sH/sRed ready from previous iteration

        // ---- GEMM1: partial Vh[r][b] over own d-chunk (float4 over d) ----
        {
            float2 acc[2][8];
            #pragma unroll
            for (int i = 0; i < 2; i++)
                #pragma unroll
                for (int b = 0; b < 8; b++) acc[i][b] = make_float2(0.f, 0.f);
            #pragma unroll
            for (int dd = 0; dd < 32; dd += 4) {
                int d = dbase1 + dd;
                float4 v0 = *(float4*)&sV[rt1*SV_STRIDE + d];
                float4 v1 = *(float4*)&sV[(rt1+128)*SV_STRIDE + d];
                #pragma unroll
                for (int b = 0; b < 8; b++) {
                    float4 hh = *(float4*)&sH[b*SH_STRIDE + d];   // broadcast
                    acc[0][b] = ffma2(lo2(v0), lo2(hh), acc[0][b]);
                    acc[0][b] = ffma2(hi2(v0), hi2(hh), acc[0][b]);
                    acc[1][b] = ffma2(lo2(v1), lo2(hh), acc[1][b]);
                    acc[1][b] = ffma2(hi2(v1), hi2(hh), acc[1][b]);
                }
            }
            #pragma unroll
            for (int i = 0; i < 2; i++)
                #pragma unroll
                for (int b = 0; b < 8; b++)
                    sRed[ks1*2048 + b*256 + rt1 + 128*i] = acc[i][b].x + acc[i][b].y;
        }
        __syncthreads();

        // combine d-halves + publish into g_vh3[t%3][s] via VECTOR reductions:
        // 512 red.global.add.v4.f32 per CTA (was 2048 scalar REDs).
        float* gbuf = g_vh3 + ((size_t)(t % 3) * NSLOTS + s) * 2048;
        {
            #pragma unroll
            for (int k = 0; k < 2; k++) {
                int c  = tid + k*256;        // v4 cell: 0..511
                int b  = c >> 6;             // 0..7
                int r4 = (c & 63) * 4;       // 0,4,...,252
                float4 p0 = *(float4*)&sRed[b*256 + r4];
                float4 p1 = *(float4*)&sRed[2048 + b*256 + r4];
                float4 v  = make_float4(p0.x + p1.x, p0.y + p1.y,
                                        p0.z + p1.z, p0.w + p1.w);
                red_add_v4(&gbuf[b*256 + r4], v);
            }
        }

        // ---- ONE barrier per step (per slot group) ----
        if (USE_CLUSTER) {
            // arrive = cluster-scope release (orders the REDs above);
            // wait   = cluster-scope acquire (orders the ldcg reads below).
            asm volatile("barrier.cluster.arrive.aligned;" ::: "memory");
            asm volatile("barrier.cluster.wait.aligned;"   ::: "memory");
        } else {
            __threadfence();
            __syncthreads();
            if (tid == 0) {
                atomicAdd(&g_bar[s], 1u);
                unsigned target = (unsigned)GROUP * (unsigned)(t + 1);
                while (*((volatile unsigned*)&g_bar[s]) < target) { }
            }
            __syncthreads();
        }

        // stage summed Vh (L2, bypass L1) and zero the buffer for step t+2
        {
            const float4* src = (const float4*)gbuf;
            #pragma unroll
            for (int k = 0; k < 2; k++) {
                int i = tid + k*256;                // 512 float4
                float4 v = __ldcg(&src[i]);
                int b = i >> 6, c4 = (i & 63) * 4;
                *(float4*)&sVh[b*SVH_STRIDE + c4] = v;
            }
            float* zbuf = g_vh3 + ((size_t)((t + 2) % 3) * NSLOTS + s) * 2048;
            if (tid < 128) zbuf[rk*128 + tid] = 0.f;
        }
        __syncthreads();

        // ---- GEMM2: Uh[d][b] = sum_r U[d][r]*Vh[b][r] (float4 over r) ----
        {
            float2 acc[2][8];
            #pragma unroll
            for (int i = 0; i < 2; i++)
                #pragma unroll
                for (int b = 0; b < 8; b++) acc[i][b] = make_float2(0.f, 0.f);
            const int rbase = ks2 * 32;
            #pragma unroll
            for (int rr = 0; rr < 32; rr += 4) {
                int r = rbase + rr;
                float4 u0 = *(float4*)&sU[dt2*SU_STRIDE + r];
                float4 u1 = *(float4*)&sU[(dt2+32)*SU_STRIDE + r];
                #pragma unroll
                for (int b = 0; b < 8; b++) {
                    float4 vh = *(float4*)&sVh[b*SVH_STRIDE + r];  // broadcast
                    acc[0][b] = ffma2(lo2(u0), lo2(vh), acc[0][b]);
                    acc[0][b] = ffma2(hi2(u0), hi2(vh), acc[0][b]);
                    acc[1][b] = ffma2(lo2(u1), lo2(vh), acc[1][b]);
                    acc[1][b] = ffma2(hi2(u1), hi2(vh), acc[1][b]);
                }
            }
            #pragma unroll
            for (int i = 0; i < 2; i++)
                #pragma unroll
                for (int b = 0; b < 8; b++)
                    sRed[ks2*512 + b*64 + dt2 + 32*i] = acc[i][b].x + acc[i][b].y;
        }
        __syncthreads();

        // epilogue: h_new = tanh(Wx + Uh); keep slice in sH, publish to hout
        {
            float* hdst = hout + ((size_t)(t+1)*8 + s)*8192;
            #pragma unroll
            for (int j = 0; j < 2; j++) {
                int b = eb + 4*j;
                float uh = 0.f;
                #pragma unroll
                for (int k = 0; k < 8; k++) uh += sRed[k*512 + b*64 + edi];
                float hn = tanhf((j == 0 ? wxp0 : wxp1) + uh);
                sH[b*SH_STRIDE + edi] = hn;
                hdst[b*1024 + dlo + edi] = hn;
            }
        }
    }
}

// ============== kernel 3: out = (sum_s C_s h[t+1,s]) * silu(z) ==============
__global__ __launch_bounds__(256) void out_kernel(const float* __restrict__ z,
                                                  const float* __restrict__ C,
                                                  const float* __restrict__ hout,
                                                  float* __restrict__ out) {
    size_t idx = (size_t)blockIdx.x * 256 + threadIdx.x;   // < T*B*D exactly
    int t   = (int)(idx >> 13);
    int rem = (int)(idx & 8191);
    float zz  = z[idx];
    float sig = 1.f / (1.f + expf(-zz));
    const float* hb = hout + ((size_t)(t+1))*65536 + rem;
    float acc = 0.f;
    #pragma unroll
    for (int s = 0; s < 8; s++) acc += C[s] * hb[(size_t)s*8192];
    out[idx] = acc * zz * sig;
}

// ================================ launch ================================
extern "C" void kernel_launch(void* const* d_in, const int* in_sizes, int n_in,
                              void* d_out, int out_size) {
    (void)in_sizes; (void)n_in; (void)out_size;
    const float* x    = (const float*)d_in[0];
    const float* z    = (const float*)d_in[1];
    const float* h0   = (const float*)d_in[2];
    const float* Wxm  = (const float*)d_in[3];
    const float* U    = (const float*)d_in[4];
    const float* V    = (const float*)d_in[5];
    const float* bias = (const float*)d_in[6];
    const float* C    = (const float*)d_in[7];

    float* out  = (float*)d_out;
    float* hout = out + (size_t)T_STEPS*BATCH*DIM;   // h region: [T+1][S][B][D]

    cudaFuncSetAttribute(recur_kernel_t<true>,
                         cudaFuncAttributeMaxDynamicSharedMemorySize, SMEM_BYTES);
    cudaFuncSetAttribute(recur_kernel_t<true>,
                         cudaFuncAttributeNonPortableClusterSizeAllowed, 1);
    cudaFuncSetAttribute(recur_kernel_t<false>,
                         cudaFuncAttributeMaxDynamicSharedMemorySize, SMEM_BYTES);

    dim3 wgrid(16, 128);
    wx_kernel<<<wgrid, 256>>>(x, Wxm, bias);

    // cluster launch config: 8 clusters x 16 CTAs (slot group == cluster)
    cudaLaunchConfig_t cfg = {};
    cfg.gridDim          = dim3(NCTAS, 1, 1);
    cfg.blockDim         = dim3(256, 1, 1);
    cfg.dynamicSmemBytes = SMEM_BYTES;
    cudaLaunchAttribute attrs[1];
    attrs[0].id = cudaLaunchAttributeClusterDimension;
    attrs[0].val.clusterDim.x = GROUP;
    attrs[0].val.clusterDim.y = 1;
    attrs[0].val.clusterDim.z = 1;
    cfg.attrs    = attrs;
    cfg.numAttrs = 1;

    int maxClusters = 0;
    cudaError_t qe = cudaOccupancyMaxActiveClusters(&maxClusters,
                                                    recur_kernel_t<true>, &cfg);
    bool use_cluster = (qe == cudaSuccess && maxClusters >= NSLOTS);
    if (!use_cluster) (void)cudaGetLastError();

    if (use_cluster) {
        cudaError_t le = cudaLaunchKernelEx(&cfg, recur_kernel_t<true>,
                                            h0, U, V, hout);
        if (le != cudaSuccess) {
            (void)cudaGetLastError();
            use_cluster = false;
        }
    }
    if (!use_cluster) {
        recur_kernel_t<false><<<NCTAS, 256, SMEM_BYTES>>>(h0, U, V, hout);
    }

    out_kernel<<<32768, 256>>>(z, C, hout, out);
}